// round 3
// baseline (speedup 1.0000x reference)
#include <cuda_runtime.h>
#include <cuda_fp16.h>
#include <cstdint>

// ---------------------------------------------------------------------------
// Problem constants
// ---------------------------------------------------------------------------
#define D_MODEL 4096
#define HIDDEN  16384
#define N_TOK   4096

// Scratch (device globals: allocation-free rule)
__device__ __align__(16) __half        g_Xh[(size_t)N_TOK * D_MODEL];       // x in fp16
__device__ __align__(16) unsigned char g_W1p[(size_t)HIDDEN * (D_MODEL/2)]; // packed nibbles
__device__ __align__(16) unsigned char g_W2p[(size_t)D_MODEL * (HIDDEN/2)];
__device__ __align__(16) __half        g_H [(size_t)N_TOK * HIDDEN];        // hidden acts fp16

// ---------------------------------------------------------------------------
// Helpers
// ---------------------------------------------------------------------------
__device__ __forceinline__ uint32_t smem_u32(const void* p) {
    uint32_t a;
    asm("{ .reg .u64 t; cvta.to.shared.u64 t, %1; cvt.u32.u64 %0, t; }" : "=r"(a) : "l"(p));
    return a;
}

#define LDMATRIX_X4(r0, r1, r2, r3, addr) \
    asm volatile("ldmatrix.sync.aligned.m8n8.x4.shared.b16 {%0,%1,%2,%3}, [%4];" \
                 : "=r"(r0), "=r"(r1), "=r"(r2), "=r"(r3) : "r"(addr))

#define MMA_16816(c0, c1, c2, c3, a0, a1, a2, a3, b0, b1) \
    asm volatile("mma.sync.aligned.m16n8k16.row.col.f32.f16.f16.f32 " \
                 "{%0,%1,%2,%3}, {%4,%5,%6,%7}, {%8,%9}, {%0,%1,%2,%3};" \
                 : "+f"(c0), "+f"(c1), "+f"(c2), "+f"(c3) \
                 : "r"(a0), "r"(a1), "r"(a2), "r"(a3), "r"(b0), "r"(b1))

// nibble-pair -> half2 via exponent trick: (0x6400|nib)==1024+nib in fp16; -1032 -> nib-8
__device__ __forceinline__ uint32_t dq_pair(uint32_t u) {
    const uint32_t OFF = 0x64086408u;
    __half2 a = *reinterpret_cast<__half2*>(&u);
    __half2 o = *reinterpret_cast<const __half2*>(&OFF);
    __half2 r = __hsub2(a, o);
    return *reinterpret_cast<uint32_t*>(&r);
}

__device__ __forceinline__ float gelu_tanh(float v) {
    float t = tanhf(0.7978845608028654f * (v + 0.044715f * v * v * v));
    return 0.5f * v * (1.0f + t);
}

// ---------------------------------------------------------------------------
// Phase 0 kernels
// ---------------------------------------------------------------------------
__global__ void convert_x_kernel(const float* __restrict__ x) {
    size_t i = (size_t)blockIdx.x * blockDim.x + threadIdx.x;  // one float4 each
    float4 v = reinterpret_cast<const float4*>(x)[i];
    __half2 a = __floats2half2_rn(v.x, v.y);
    __half2 b = __floats2half2_rn(v.z, v.w);
    uint2 u;
    u.x = *reinterpret_cast<uint32_t*>(&a);
    u.y = *reinterpret_cast<uint32_t*>(&b);
    reinterpret_cast<uint2*>(g_Xh)[i] = u;
}

__global__ void repack_kernel(const int* __restrict__ in, int which) {
    unsigned char* out = which ? g_W2p : g_W1p;
    size_t i = (size_t)blockIdx.x * blockDim.x + threadIdx.x;  // 4 int32 -> 4 bytes
    int4 p = reinterpret_cast<const int4*>(in)[i];
    uint32_t u = (uint32_t)(p.x & 0xFF) | ((uint32_t)(p.y & 0xFF) << 8) |
                 ((uint32_t)(p.z & 0xFF) << 16) | ((uint32_t)(p.w & 0xFF) << 24);
    reinterpret_cast<uint32_t*>(out)[i] = u;
}

// ---------------------------------------------------------------------------
// GEMM: C[m,n] = sum_k A[m,k] * nib(Bp)[n,k] ; epilogue applies scales[n] (+gelu)
// A fp16 [Mtot,K] row-major; Bp uint8 [Ntot, K/2].
// CTA tile 128x128, BK=64. 256 thr = 8 warps as 2(m) x 4(n); warp tile 64x32.
// Smem: A tile 16KB + B tile 16KB, SW128 swizzle:
//   addr(row,c) = base + row*128 + (c ^ ((row&7)<<4)),  c in [0,128)
// ---------------------------------------------------------------------------
template <bool GELU>
__device__ __forceinline__ void gemm_body(const __half* __restrict__ A,
                                          const unsigned char* __restrict__ Bp,
                                          const float* __restrict__ scales,
                                          int K, __half* __restrict__ outH,
                                          float* __restrict__ outF, int ldOut) {
    __shared__ unsigned char smem_raw[32768 + 1024];
    const int tid = threadIdx.x;
    const int w = tid >> 5, lane = tid & 31;
    const int wm = w & 1, wn = w >> 1;

    uint32_t raw = smem_u32(smem_raw);
    uint32_t base = (raw + 1023u) & ~1023u;
    unsigned char* sptr = smem_raw + (base - raw);
    const uint32_t smA = base;          // 16 KB
    const uint32_t smB = base + 16384;  // 16 KB

    const int m0 = blockIdx.y * 128;
    const int n0 = blockIdx.x * 128;
    const int ldBp = K >> 1;
    const int kIters = K >> 6;

    // ---- global load addressing (per thread, per iteration) ----
    // A tile: 128 rows x 128B = 1024 x 16B -> 4 uint4/thread
    const int arows[4] = { tid >> 3, (tid >> 3) + 32, (tid >> 3) + 64, (tid >> 3) + 96 };
    const int acb = (tid & 7) * 16;  // byte col in 128B row
    const uint32_t asw = acb ^ (((tid >> 3) & 7) << 4);  // same for all 4 (rows differ by 32)
    const __half* aptr[4];
#pragma unroll
    for (int j = 0; j < 4; ++j)
        aptr[j] = A + (size_t)(m0 + arows[j]) * K + (tid & 7) * 8;
    // B tile: 128 rows x 32B packed = 256 x 16B -> 1 uint4/thread (-> 64B smem)
    const int rb = tid >> 1;
    const int bhalf = tid & 1;
    const unsigned char* bptr = Bp + (size_t)(n0 + rb) * ldBp + bhalf * 16;
    const uint32_t bxor_sts = ((rb & 7) << 4);

    // ---- ldmatrix lane addressing ----
    const uint32_t lxor = (uint32_t)((lane & 7) << 4);
    // A: 4 m16 frags at rows wm*64 + mf*16 + (lane&7) + ((lane>>3)&1)*8 ; kb += ((lane>>4)&1)*16
    uint32_t aBase[4];
    {
        int r = wm * 64 + (lane & 7) + ((lane >> 3) & 1) * 8;
#pragma unroll
        for (int mf = 0; mf < 4; ++mf) aBase[mf] = smA + (uint32_t)((r + mf * 16) * 128);
    }
    const uint32_t akb = (uint32_t)(((lane >> 4) & 1) * 16);
    // B: 2 n16 blocks at rows wn*32 + nb*16 + (lane&7) + ((lane>>4)&1)*8 ; kb += ((lane>>3)&1)*16
    uint32_t bBase[2];
    {
        int r = wn * 32 + (lane & 7) + ((lane >> 4) & 1) * 8;
#pragma unroll
        for (int nb = 0; nb < 2; ++nb) bBase[nb] = smB + (uint32_t)((r + nb * 16) * 128);
    }
    const uint32_t bkb = (uint32_t)(((lane >> 3) & 1) * 16);

    float acc[4][4][4];
#pragma unroll
    for (int i = 0; i < 4; ++i)
#pragma unroll
        for (int j = 0; j < 4; ++j)
#pragma unroll
            for (int e = 0; e < 4; ++e) acc[i][j][e] = 0.0f;

    // ---- prologue: load iter 0 ----
    uint4 av[4], bv;
#pragma unroll
    for (int j = 0; j < 4; ++j) av[j] = *reinterpret_cast<const uint4*>(aptr[j]);
    bv = *reinterpret_cast<const uint4*>(bptr);

    for (int it = 0; it < kIters; ++it) {
        __syncthreads();  // previous compute's smem reads complete

        // ---- store A (swizzled) ----
#pragma unroll
        for (int j = 0; j < 4; ++j)
            *reinterpret_cast<uint4*>(sptr + (smA - base) + arows[j] * 128 + asw) = av[j];
        // ---- dequant + store B (swizzled) ----
        {
            const uint32_t* ws = reinterpret_cast<const uint32_t*>(&bv);
            const int hb = bhalf * 64;
#pragma unroll
            for (int i = 0; i < 4; ++i) {
                uint32_t ww = ws[i];
                uint32_t his = (ww >> 4) & 0x0F0F0F0Fu;
                uint32_t los = ww & 0x0F0F0F0Fu;
                uint4 st;
                st.x = dq_pair((__byte_perm(his, los, 0x0400) & 0x00FF00FFu) | 0x64006400u);
                st.y = dq_pair((__byte_perm(his, los, 0x0501) & 0x00FF00FFu) | 0x64006400u);
                st.z = dq_pair((__byte_perm(his, los, 0x0602) & 0x00FF00FFu) | 0x64006400u);
                st.w = dq_pair((__byte_perm(his, los, 0x0703) & 0x00FF00FFu) | 0x64006400u);
                uint32_t c = (uint32_t)(hb + i * 16) ^ bxor_sts;
                *reinterpret_cast<uint4*>(sptr + 16384 + rb * 128 + c) = st;
            }
        }
        __syncthreads();

        // ---- prefetch next iteration's globals (overlaps with MMA below) ----
        if (it + 1 < kIters) {
            const int k0 = (it + 1) << 6;
#pragma unroll
            for (int j = 0; j < 4; ++j)
                av[j] = *reinterpret_cast<const uint4*>(aptr[j] + k0);
            bv = *reinterpret_cast<const uint4*>(bptr + (k0 >> 1));
        }

        // ---- compute: 4 k-steps of 16 ----
#pragma unroll
        for (int s = 0; s < 4; ++s) {
            const uint32_t ca = ((uint32_t)(s * 32) + akb) ^ lxor;
            const uint32_t cb = ((uint32_t)(s * 32) + bkb) ^ lxor;
            uint32_t af[4][4];
#pragma unroll
            for (int mf = 0; mf < 4; ++mf)
                LDMATRIX_X4(af[mf][0], af[mf][1], af[mf][2], af[mf][3], aBase[mf] + ca);
            uint32_t bf[2][4];
#pragma unroll
            for (int nb = 0; nb < 2; ++nb)
                LDMATRIX_X4(bf[nb][0], bf[nb][1], bf[nb][2], bf[nb][3], bBase[nb] + cb);
#pragma unroll
            for (int mf = 0; mf < 4; ++mf)
#pragma unroll
                for (int nf = 0; nf < 4; ++nf) {
                    uint32_t b0 = bf[nf >> 1][(nf & 1) * 2];
                    uint32_t b1 = bf[nf >> 1][(nf & 1) * 2 + 1];
                    MMA_16816(acc[mf][nf][0], acc[mf][nf][1], acc[mf][nf][2], acc[mf][nf][3],
                              af[mf][0], af[mf][1], af[mf][2], af[mf][3], b0, b1);
                }
        }
    }

    // ---- epilogue: scales (+gelu), direct gmem stores ----
    const int mrow0 = m0 + wm * 64 + (lane >> 2);
    const int ncol0 = n0 + wn * 32 + (lane & 3) * 2;
#pragma unroll
    for (int nf = 0; nf < 4; ++nf) {
        const int col = ncol0 + nf * 8;
        const float s0 = __ldg(scales + col);
        const float s1 = __ldg(scales + col + 1);
#pragma unroll
        for (int mf = 0; mf < 4; ++mf) {
            const int r = mrow0 + mf * 16;
            float v0 = acc[mf][nf][0] * s0, v1 = acc[mf][nf][1] * s1;
            float v2 = acc[mf][nf][2] * s0, v3 = acc[mf][nf][3] * s1;
            if (GELU) {
                __half2 h0 = __floats2half2_rn(gelu_tanh(v0), gelu_tanh(v1));
                __half2 h1 = __floats2half2_rn(gelu_tanh(v2), gelu_tanh(v3));
                *reinterpret_cast<__half2*>(outH + (size_t)r * ldOut + col) = h0;
                *reinterpret_cast<__half2*>(outH + (size_t)(r + 8) * ldOut + col) = h1;
            } else {
                float2 f0 = make_float2(v0, v1);
                float2 f1 = make_float2(v2, v3);
                *reinterpret_cast<float2*>(outF + (size_t)r * ldOut + col) = f0;
                *reinterpret_cast<float2*>(outF + (size_t)(r + 8) * ldOut + col) = f1;
            }
        }
    }
}

__global__ void __launch_bounds__(256, 2)
gemm1_kernel(const float* __restrict__ scales) {
    gemm_body<true>(g_Xh, g_W1p, scales, D_MODEL, g_H, nullptr, HIDDEN);
}

__global__ void __launch_bounds__(256, 2)
gemm2_kernel(const float* __restrict__ scales, float* __restrict__ out) {
    gemm_body<false>(g_H, g_W2p, scales, HIDDEN, nullptr, out, D_MODEL);
}

// ---------------------------------------------------------------------------
// Launch
// ---------------------------------------------------------------------------
extern "C" void kernel_launch(void* const* d_in, const int* in_sizes, int n_in,
                              void* d_out, int out_size) {
    const float* x    = (const float*)d_in[0];
    const int*   fc1p = (const int*)d_in[1];
    const float* s1   = (const float*)d_in[2];
    const int*   fc2p = (const int*)d_in[3];
    const float* s2   = (const float*)d_in[4];
    float* out = (float*)d_out;

    convert_x_kernel<<<(N_TOK * (size_t)D_MODEL) / 4 / 256, 256>>>(x);
    repack_kernel<<<((size_t)HIDDEN * (D_MODEL / 2)) / 4 / 256, 256>>>(fc1p, 0);
    repack_kernel<<<((size_t)D_MODEL * (HIDDEN / 2)) / 4 / 256, 256>>>(fc2p, 1);

    gemm1_kernel<<<dim3(HIDDEN / 128, N_TOK / 128), 256>>>(s1);
    gemm2_kernel<<<dim3(D_MODEL / 128, N_TOK / 128), 256>>>(s2, out);
}